// round 3
// baseline (speedup 1.0000x reference)
#include <cuda_runtime.h>

// ActiveParticles step, N=4096.
// Inputs: positions[N,2] f32, orientations[N,2] f32, Deltas[1] f32,
//         rot_noise[N] f32, trans_noise[N,2] f32.
// Output: [5, N, 2] f32 = {new_p, new_u, orientation_sums, leftturns, rightturns}.

#define NMAX 4096

static __device__ float2 g_cms;
static __device__ float4 g_pu[NMAX];            // (p.x, p.y, u.x, u.y)
static __device__ float4 g_posA4[NMAX / 2];     // positions ping (float2 pairs)
static __device__ float4 g_posB4[NMAX / 2];     // positions pong

__device__ __forceinline__ float wsum(float v) {
#pragma unroll
    for (int o = 16; o; o >>= 1) v += __shfl_xor_sync(0xffffffffu, v, o);
    return v;
}

__device__ __forceinline__ float anglewrap(float diff) {
    const float PI_F = 3.1415927410125732f;
    if (diff <= -PI_F) diff = diff - PI_F * floorf(diff / PI_F);  // jnp.mod(diff, PI)
    if (diff >= PI_F) diff -= 2.0f * PI_F;
    return diff;
}

__device__ __forceinline__ float anglediff(float ax, float ay, float bx, float by) {
    return anglewrap(atan2f(ay, ax) - atan2f(by, bx));
}

// ------------- prep: pack (p,u) -> g_pu (all blocks); block 0 computes mean -------
__global__ void prep_kernel(const float2* __restrict__ p, const float2* __restrict__ u, int n) {
    int i = blockIdx.x * blockDim.x + threadIdx.x;
    if (i < n) {
        float2 pp = p[i], uu = u[i];
        g_pu[i] = make_float4(pp.x, pp.y, uu.x, uu.y);
    }
    if (blockIdx.x == 0) {
        __shared__ float2 sh[32];
        float sx = 0.f, sy = 0.f;
        for (int j = threadIdx.x; j < n; j += blockDim.x) {
            float2 v = p[j];
            sx += v.x; sy += v.y;
        }
        sx = wsum(sx); sy = wsum(sy);
        int lane = threadIdx.x & 31, w = threadIdx.x >> 5;
        if (lane == 0) sh[w] = make_float2(sx, sy);
        __syncthreads();
        if (w == 0) {
            int nw = blockDim.x >> 5;
            float2 v = (lane < nw) ? sh[lane] : make_float2(0.f, 0.f);
            float ax = wsum(v.x), ay = wsum(v.y);
            if (lane == 0) {
                float inv = 1.0f / fmaxf((float)n, 1.0f);   // max(n_a,1), n_a = n
                g_cms = make_float2(ax * inv, ay * inv);
            }
        }
    }
}

// ---------------- main pairwise pass: 2 warps per particle ------------------------
// Block = 256 threads = 8 warps = 4 particles. Grid = n/4.
__global__ void __launch_bounds__(256) main_kernel(
        const float* __restrict__ deltas, const float* __restrict__ rnoise,
        const float* __restrict__ tnoise_, float* __restrict__ out, int n) {
    const float2* tn = (const float2*)tnoise_;
    __shared__ float red[8][5];

    const int w    = threadIdx.x >> 5;          // warp in block: 0..7
    const int lane = threadIdx.x & 31;
    const int i    = blockIdx.x * 4 + (w >> 1); // particle
    const int h    = w & 1;                     // which half of j-range

    const float4 me = g_pu[i];
    const float pix = me.x, piy = me.y;

    const float RR2  = (float)(8e-6 * 8e-6);
    const float ROCf = (float)(2.5e-5 + 3.15e-6);
    const float ROC2 = ROCf * ROCf;

    float nr = 0.f, srx = 0.f, sry = 0.f, osx = 0.f, osy = 0.f;

    const int half = n >> 1;                    // 2048
    const int start = h * half;
    for (int base = start; base < start + half; base += 128) {
        float4 a0 = g_pu[base + lane];
        float4 a1 = g_pu[base + lane + 32];
        float4 a2 = g_pu[base + lane + 64];
        float4 a3 = g_pu[base + lane + 96];
#pragma unroll
        for (int k = 0; k < 4; k++) {
            float4 a = (k == 0) ? a0 : (k == 1) ? a1 : (k == 2) ? a2 : a3;
            float dx = a.x - pix, dy = a.y - piy;
            float d2 = fmaf(dx, dx, dy * dy);
            if (d2 <= ROC2) {                       // rare (~3 neighbors / 4096)
                osx += a.z; osy += a.w;             // mask_ro (includes j==i)
                if (d2 <= RR2 && d2 > 0.f) {        // inside_Rr (d2>0 <=> j!=i)
                    // in_front: wrap(angle(dir)-angle(u_j)) < pi/2
                    //   <=> !(dot<=0 && cross>=0)
                    float c = dx * a.z + dy * a.w;
                    float s = a.z * dy - a.w * dx;
                    if (!(c <= 0.0f && s >= 0.0f)) { nr += 1.f; srx += a.x; sry += a.y; }
                }
            }
        }
    }
    nr = wsum(nr); srx = wsum(srx); sry = wsum(sry); osx = wsum(osx); osy = wsum(osy);
    if (lane == 0) {
        red[w][0] = nr; red[w][1] = srx; red[w][2] = sry; red[w][3] = osx; red[w][4] = osy;
    }
    __syncthreads();

    // ---- per-particle epilogue: threads 0..3 each finish one particle ----
    if (threadIdx.x < 4) {
        const int ii = blockIdx.x * 4 + threadIdx.x;
        const int w0 = threadIdx.x * 2;
        float nrT  = red[w0][0] + red[w0 + 1][0];
        float srxT = red[w0][1] + red[w0 + 1][1];
        float sryT = red[w0][2] + red[w0 + 1][2];
        float osxT = red[w0][3] + red[w0 + 1][3];
        float osyT = red[w0][4] + red[w0 + 1][4];

        const float4 m = g_pu[ii];
        const float px = m.x, py = m.y, ux = m.z, uy = m.w;

        float sgn = (nrT > 0.f) ? 1.0f : 0.0f;
        float invr = 1.0f / fmaxf(nrT, 1.0f);
        float dax = -(srxT * invr - px * sgn);
        float day = -(sryT * invr - py * sgn);

        float2 cms = g_cms;
        float Psx = cms.x - px;                 // sign(n_a) == 1
        float Psy = cms.y - py;

        float Delta = __ldg(&deltas[0]);
        float cd = cosf(Delta), sd = sinf(Delta);
        float lx = Psx * cd - Psy * sd, ly = Psx * sd + Psy * cd;  // Ps*e^{+iD}
        float rx = Psx * cd + Psy * sd, ry = Psy * cd - Psx * sd;  // Ps*e^{-iD}

        const float EPSF = 1e-14f;
        float nb  = fmaxf(sqrtf(osxT * osxT + osyT * osyT + 1e-30f), EPSF);
        float naL = fmaxf(sqrtf(lx * lx + ly * ly + 1e-30f), EPSF);
        float naR = fmaxf(sqrtf(rx * rx + ry * ry + 1e-30f), EPSF);
        float csL = (lx * osxT + ly * osyT) / (naL * nb);
        float csR = (rx * osxT + ry * osyT) / (naR * nb);
        bool left_closer = (csL >= csR);
        float bx = left_closer ? lx : rx;
        float by = left_closer ? ly : ry;

        float d_abs = sqrtf(dax * dax + day * day);
        float ang;
        if (d_abs > 0.f) {
            ang = anglediff(dax, day, ux, uy);
        } else {
            float babs = sqrtf(bx * bx + by * by);
            float bsx = (babs > 0.f) ? bx : 1.0f;
            float bsy = (babs > 0.f) ? by : 0.0f;
            ang = anglediff(bsx, bsy, ux, uy);
        }

        const float C1   = (float)(0.2 * 25.0 * 0.0028);
        const float S2DR = (float)0.07483314773547883;    // sqrt(2*DR)
        const float SDT  = (float)0.4472135954999579;     // sqrt(dt)
        float phi = C1 * sinf(ang) + rnoise[ii] * S2DR * SDT;
        float cr = cosf(phi), sr = sinf(phi);
        float nux = ux * cr - uy * sr;
        float nuy = ux * sr + uy * cr;

        const float DTV = (float)(0.2 * 5e-7);
        const float CSH = (float)0.7071067811865476;      // sqrt(0.5)
        const float C2T = (float)1.6733200530681511e-07;  // sqrt(2*DT_trans)
        float2 t = __ldg(&tn[ii]);
        float tx = DTV * ux + ((t.x * CSH) * C2T) * SDT;
        float ty = DTV * uy + ((t.y * CSH) * C2T) * SDT;

        ((float2*)g_posA4)[ii] = make_float2(px + tx, py + ty);
        int b = 2 * n;
        out[1 * b + 2 * ii + 0] = nux;  out[1 * b + 2 * ii + 1] = nuy;
        out[2 * b + 2 * ii + 0] = osxT; out[2 * b + 2 * ii + 1] = osyT;
        out[3 * b + 2 * ii + 0] = lx;   out[3 * b + 2 * ii + 1] = ly;
        out[4 * b + 2 * ii + 0] = rx;   out[4 * b + 2 * ii + 1] = ry;
    }
}

// ---------------- collision sweep: 2 warps per particle ---------------------------
// pass 0: A->B, pass 1: B->A, pass 2: A->out_final
__global__ void __launch_bounds__(256) collide_kernel(int pass, float2* __restrict__ out_final, int n) {
    const float4* src4 = (pass == 1) ? g_posB4 : g_posA4;
    float2* dst = (pass == 0) ? (float2*)g_posB4 : (pass == 1) ? (float2*)g_posA4 : out_final;
    __shared__ float red[8][2];

    const int w    = threadIdx.x >> 5;
    const int lane = threadIdx.x & 31;
    const int i    = blockIdx.x * 4 + (w >> 1);
    const int h    = w & 1;

    const float2 pi = ((const float2*)src4)[i];
    const float TH2 = (float)(2.0 * 3.15e-6) * (float)(2.0 * 3.15e-6);
    const float C21 = (float)(2.1 * 3.15e-6);

    float mvx = 0.f, mvy = 0.f;
    const int hq = n >> 2;                      // float4 count per half = 1024
    const int f0 = h * hq;
    for (int fb = f0; fb < f0 + hq; fb += 128) {
        float4 q0 = src4[fb + lane];
        float4 q1 = src4[fb + lane + 32];
        float4 q2 = src4[fb + lane + 64];
        float4 q3 = src4[fb + lane + 96];
#pragma unroll
        for (int k = 0; k < 4; k++) {
            float4 v = (k == 0) ? q0 : (k == 1) ? q1 : (k == 2) ? q2 : q3;
            float dxa = v.x - pi.x, dya = v.y - pi.y;
            float dxb = v.z - pi.x, dyb = v.w - pi.y;
            float d2a = fmaf(dxa, dxa, dya * dya);
            float d2b = fmaf(dxb, dxb, dyb * dyb);
            bool hitA = (d2a <= TH2) && (d2a > 0.f);   // d2>0 <=> j!=i
            bool hitB = (d2b <= TH2) && (d2b > 0.f);
            if (hitA || hitB) {                        // rare
                if (hitA) {
                    float ab = sqrtf(d2a);
                    float sc = (C21 - ab) * 0.5f / ab;
                    mvx += dxa * sc; mvy += dya * sc;
                }
                if (hitB) {
                    float ab = sqrtf(d2b);
                    float sc = (C21 - ab) * 0.5f / ab;
                    mvx += dxb * sc; mvy += dyb * sc;
                }
            }
        }
    }
    mvx = wsum(mvx); mvy = wsum(mvy);
    if (lane == 0) { red[w][0] = mvx; red[w][1] = mvy; }
    __syncthreads();
    if (threadIdx.x < 4) {
        const int ii = blockIdx.x * 4 + threadIdx.x;
        const int w0 = threadIdx.x * 2;
        float mx = red[w0][0] + red[w0 + 1][0];
        float my = red[w0][1] + red[w0 + 1][1];
        float2 pv = ((const float2*)src4)[ii];
        dst[ii] = make_float2(pv.x - mx, pv.y - my);
    }
}

extern "C" void kernel_launch(void* const* d_in, const int* in_sizes, int n_in,
                              void* d_out, int out_size) {
    const float* pos = (const float*)d_in[0];
    const float* ori = (const float*)d_in[1];
    const float* del = (const float*)d_in[2];
    const float* rno = (const float*)d_in[3];
    const float* tno = (const float*)d_in[4];
    float* out = (float*)d_out;
    const int n = in_sizes[3];                  // rot_noise has N elements

    const int blocks = n / 4;                   // 4 particles per 256-thread block

    prep_kernel<<<(n + 1023) / 1024, 1024>>>((const float2*)pos, (const float2*)ori, n);
    main_kernel<<<blocks, 256>>>(del, rno, tno, out, n);
    collide_kernel<<<blocks, 256>>>(0, nullptr, n);
    collide_kernel<<<blocks, 256>>>(1, nullptr, n);
    collide_kernel<<<blocks, 256>>>(2, (float2*)out, n);
}